// round 15
// baseline (speedup 1.0000x reference)
#include <cuda_runtime.h>
#include <cuda_fp16.h>
#include <math.h>

#define MAXN 100000
#define HID 256
#define C 10
#define HEADS 4
#define TSTEPS 12

extern __shared__ char smem_dyn[];

__device__ unsigned g_wx[4096];
__device__ unsigned g_w1[8*4096];
__device__ unsigned g_w2[16*4096];
__device__ unsigned g_hout[(MAXN+128)*12*64];
__device__ float g_cW1t[HID*128];
__device__ float g_probs[MAXN*C];
__device__ float g_x[MAXN*HEADS*C];
__device__ float g_as[MAXN*HEADS];
__device__ float g_ad[MAXN*HEADS];
__device__ float g_ssum[MAXN*HEADS];
__device__ float g_gout[MAXN*HEADS*C];
__device__ float g_deg[MAXN];
__device__ float g_nsum[MAXN*C];
__device__ float g_econf[MAXN];
__device__ float g_tconf[MAXN];
__device__ float g_maxp[MAXN];
__device__ float g_unc[MAXN];
__device__ int   g_lab[MAXN];

__device__ __forceinline__ unsigned pkhf(float a,float b){
  return (unsigned)__half_as_ushort(__float2half(a))
       |((unsigned)__half_as_ushort(__float2half(b))<<16);}
__device__ __forceinline__ unsigned pk2f(float lo,float hi){
  unsigned r;asm("cvt.rn.f16x2.f32 %0,%1,%2;":"=r"(r):"f"(hi),"f"(lo));return r;}
__device__ __forceinline__ unsigned th2(unsigned x){unsigned y;asm("tanh.approx.f16x2 %0,%1;":"=r"(y):"r"(x));return y;}
__device__ __forceinline__ unsigned h2mul(unsigned a,unsigned b){unsigned r;asm("mul.f16x2 %0,%1,%2;":"=r"(r):"r"(a),"r"(b));return r;}
__device__ __forceinline__ unsigned h2fma(unsigned a,unsigned b,unsigned c){unsigned r;asm("fma.rn.f16x2 %0,%1,%2,%3;":"=r"(r):"r"(a),"r"(b),"r"(c));return r;}
#define H05 0x38003800u
__device__ __forceinline__ unsigned sg2(unsigned x){return h2fma(th2(h2mul(x,H05)),H05,H05);}
__device__ __forceinline__ void cpa16(char* s,const char* g){unsigned a=(unsigned)__cvta_generic_to_shared(s);asm volatile("cp.async.cg.shared.global [%0],[%1],16;"::"r"(a),"l"(g));}
__device__ __forceinline__ void cpcommit(){asm volatile("cp.async.commit_group;");}
__device__ __forceinline__ void cpwait(){asm volatile("cp.async.wait_group 0;");}
__device__ __forceinline__ void red4(float* p,float a,float b,float c,float d){
  asm volatile("red.global.add.v4.f32 [%0],{%1,%2,%3,%4};"::"l"(p),"f"(a),"f"(b),"f"(c),"f"(d):"memory");}
__device__ __forceinline__ void red1(float* p,float a){
  asm volatile("red.global.add.f32 [%0],%1;"::"l"(p),"f"(a):"memory");}
#define MMAH(c0,c1,a,b0,b1) asm volatile("mma.sync.aligned.m16n8k16.row.col.f16.f16.f16.f16 {%0,%1},{%2,%3,%4,%5},{%6,%7},{%0,%1};":"+r"(c0),"+r"(c1):"r"(a[0]),"r"(a[1]),"r"(a[2]),"r"(a[3]),"r"(b0),"r"(b1))

// ---------------- prep (weights only, main stream) ----------------
__global__ void k_prep_w(const float* __restrict__ w_ih0,const float* __restrict__ w_hh0,
                         const float* __restrict__ w_ih1,const float* __restrict__ w_hh1){
  long i=(long)blockIdx.x*blockDim.x+threadIdx.x; long st=(long)gridDim.x*blockDim.x;
  for(long idx=i;idx<4096;idx+=st){
    int reg=(int)idx&1,lane=((int)idx>>1)&31,nt=(int)idx>>6;
    int nn=nt*8+(lane>>2),k0=(lane&3)*2+reg*8;
    float lo=(k0<C)?w_ih0[nn*C+k0]:0.f,hi=(k0+1<C)?w_ih0[nn*C+k0+1]:0.f;
    g_wx[idx]=pkhf(lo,hi);}
  for(long idx=i;idx<8*4096;idx+=st){
    int kc=(int)idx>>12,r=(int)idx&4095,reg=r&1,lane=(r>>1)&31,nt=r>>6;
    int nn=nt*8+(lane>>2),k0=kc*16+(lane&3)*2+reg*8;
    g_w1[idx]=pkhf(w_hh0[nn*128+k0],w_hh0[nn*128+k0+1]);}
  for(long idx=i;idx<16*4096;idx+=st){
    int kc=(int)idx>>12,r=(int)idx&4095,reg=r&1,lane=(r>>1)&31,nt=r>>6;
    int nn=nt*8+(lane>>2),k0=kc*16+(lane&3)*2+reg*8;
    float lo=(k0<128)?w_ih1[nn*128+k0]:w_hh1[nn*128+k0-128];
    float hi=(k0<128)?w_ih1[nn*128+k0+1]:w_hh1[nn*128+k0-127];
    g_w2[idx]=pkhf(lo,hi);}
}

// ---------------- zero + cW1 transpose (side stream) ----------------
__global__ void k_zero(const float* __restrict__ cW1,int n){
  long i=(long)blockIdx.x*blockDim.x+threadIdx.x; long st=(long)gridDim.x*blockDim.x;
  for(long idx=i;idx<HID*128;idx+=st){int k=(int)(idx/128),o=(int)(idx%128);g_cW1t[idx]=cW1[o*HID+k];}
  for(long idx=i;idx<(long)n*HEADS;idx+=st)g_ssum[idx]=0.f;
  for(long idx=i;idx<(long)n*HEADS*C;idx+=st)g_gout[idx]=0.f;
  for(long idx=i;idx<n;idx+=st)g_deg[idx]=0.f;
  for(long idx=i;idx<(long)n*C;idx+=st)g_nsum[idx]=0.f;
}

// ---------------- stage1 ----------------
__global__ void k_stage1(const float* __restrict__ preds,const float* __restrict__ gW,
                         const float* __restrict__ gas,const float* __restrict__ gad,int n){
  __shared__ float sgW[C*HEADS*C],sas[HEADS*C],sad[HEADS*C];
  int t=threadIdx.x;
  for(int i=t;i<C*HEADS*C;i+=blockDim.x)sgW[i]=gW[i];
  if(t<HEADS*C){sas[t]=gas[t];sad[t]=gad[t];}
  __syncthreads();
  int i=blockIdx.x*blockDim.x+t; if(i>=n)return;
  float p[C];float m=-1e30f;
  #pragma unroll
  for(int c=0;c<C;c++){p[c]=preds[i*C+c];m=fmaxf(m,p[c]);}
  float s=0.f;
  #pragma unroll
  for(int c=0;c<C;c++){p[c]=expf(p[c]-m);s+=p[c];}
  float inv=1.f/s;int lab=0;float mp=-1.f,ent=0.f;
  #pragma unroll
  for(int c=0;c<C;c++){p[c]*=inv;if(p[c]>mp){mp=p[c];lab=c;}}
  #pragma unroll
  for(int c=0;c<C;c++){ent-=p[c]*logf(p[c]+1e-8f);g_probs[i*C+c]=p[c];}
  g_lab[i]=lab;g_maxp[i]=mp;g_unc[i]=ent/2.302585093f;
  float xv[HEADS*C];
  #pragma unroll
  for(int hc=0;hc<HEADS*C;hc++){float a=0.f;
    #pragma unroll
    for(int c=0;c<C;c++)a+=p[c]*sgW[c*(HEADS*C)+hc];
    xv[hc]=a;g_x[(long)i*(HEADS*C)+hc]=a;}
  #pragma unroll
  for(int h=0;h<HEADS;h++){float a=0.f,b=0.f;
    #pragma unroll
    for(int c=0;c<C;c++){a+=xv[h*C+c]*sas[h*C+c];b+=xv[h*C+c]*sad[h*C+c];}
    g_as[i*HEADS+h]=a;g_ad[i*HEADS+h]=b;}
}

// ---------------- confidence net: 32 nodes/CTA, W1 from L2 ----------------
__global__ void __launch_bounds__(256) k_conf(const float* __restrict__ emb,const float* __restrict__ cb1,
                                              const float* __restrict__ cW2,const float* __restrict__ cb2,int n){
  float* sE=(float*)smem_dyn;
  int t=threadIdx.x;int node0=blockIdx.x*32;
  for(int idx=t;idx<8192;idx+=256){int nl=idx>>8,k=idx&255;sE[idx]=(node0+nl<n)?emb[(long)(node0+nl)*HID+k]:0.f;}
  __syncthreads();
  int j4=t&31,r=t>>5;
  float acc[4][4];
  #pragma unroll
  for(int a=0;a<4;a++){acc[a][0]=0;acc[a][1]=0;acc[a][2]=0;acc[a][3]=0;}
  for(int k=0;k<HID;k+=4){
    float4 w0=__ldg((const float4*)&g_cW1t[(k+0)*128+j4*4]);
    float4 w1=__ldg((const float4*)&g_cW1t[(k+1)*128+j4*4]);
    float4 w2=__ldg((const float4*)&g_cW1t[(k+2)*128+j4*4]);
    float4 w3=__ldg((const float4*)&g_cW1t[(k+3)*128+j4*4]);
    #pragma unroll
    for(int i=0;i<4;i++){
      float4 e=*(const float4*)&sE[(r*4+i)*HID+k];
      acc[i][0]=fmaf(e.x,w0.x,fmaf(e.y,w1.x,fmaf(e.z,w2.x,fmaf(e.w,w3.x,acc[i][0]))));
      acc[i][1]=fmaf(e.x,w0.y,fmaf(e.y,w1.y,fmaf(e.z,w2.y,fmaf(e.w,w3.y,acc[i][1]))));
      acc[i][2]=fmaf(e.x,w0.z,fmaf(e.y,w1.z,fmaf(e.z,w2.z,fmaf(e.w,w3.z,acc[i][2]))));
      acc[i][3]=fmaf(e.x,w0.w,fmaf(e.y,w1.w,fmaf(e.z,w2.w,fmaf(e.w,w3.w,acc[i][3]))));}}
  float b1[4],w2v[4];
  #pragma unroll
  for(int cc=0;cc<4;cc++){b1[cc]=cb1[j4*4+cc];w2v[cc]=cW2[j4*4+cc];}
  float b2=cb2[0];
  #pragma unroll
  for(int i=0;i<4;i++){
    float pi=0.f;
    #pragma unroll
    for(int cc=0;cc<4;cc++){float h=fmaxf(acc[i][cc]+b1[cc],0.f);pi=fmaf(h,w2v[cc],pi);}
    #pragma unroll
    for(int off=16;off>0;off>>=1)pi+=__shfl_xor_sync(0xffffffffu,pi,off);
    if(j4==0){int node=node0+r*4+i;if(node<n)g_econf[node]=1.f/(1.f+__expf(-(pi+b2)));}
  }
}

// ---------------- LSTM: f16-acc mma, 128 nodes/CTA ----------------
__device__ __forceinline__ void chunkH(unsigned acc[8][4][2],unsigned abase,int kb,
                                       const unsigned* pan,int w,int lane){
  unsigned b[4][2];
  #pragma unroll
  for(int g=0;g<4;g++){const unsigned* bp=&pan[((g*16+w)*32+lane)*2];b[g][0]=bp[0];b[g][1]=bp[1];}
  #pragma unroll
  for(int mt=0;mt<8;mt++){
    unsigned af[4];
    unsigned a=abase+mt*16*528+kb*2;
    asm volatile("ldmatrix.sync.aligned.m8n8.x4.shared.b16 {%0,%1,%2,%3},[%4];"
      :"=r"(af[0]),"=r"(af[1]),"=r"(af[2]),"=r"(af[3]):"r"(a));
    #pragma unroll
    for(int g=0;g<4;g++)MMAH(acc[mt][g][0],acc[mt][g][1],af,b[g][0],b[g][1]);
  }
}

__global__ void __launch_bounds__(512,1) k_lstm(const float* __restrict__ preds,
    const float* __restrict__ b_ih0,const float* __restrict__ b_hh0,
    const float* __restrict__ b_ih1,const float* __restrict__ b_hh1,int n){
  char* sm=smem_dyn;
  unsigned* pan0=(unsigned*)sm; unsigned* pan1=(unsigned*)(sm+16384);
  unsigned* sWX=(unsigned*)(sm+32768);
  __half* sH=(__half*)(sm+49152);     // [128][264]
  __half* sX=(__half*)(sm+116736);    // [128][24]
  float* sB1=(float*)(sm+122880);
  float* sB2=(float*)(sm+124928);
  int t=threadIdx.x,w=t>>5,lane=t&31,gid=lane>>2,tg=lane&3;
  int node0=blockIdx.x*128;
  for(int idx=t;idx<2048;idx+=512){int r=idx>>4,c2=idx&15;
    sX[r*24+c2]=__float2half((c2<C&&node0+r<n)?preds[(long)(node0+r)*C+c2]:0.f);}
  for(int idx=t;idx<4096;idx+=512)sWX[idx]=g_wx[idx];
  sB1[t]=b_ih0[t]+b_hh0[t]; sB2[t]=b_ih1[t]+b_hh1[t];
  for(int idx=t;idx<16896;idx+=512)((unsigned*)sH)[idx]=0;
  __syncthreads();
  unsigned shb=(unsigned)__cvta_generic_to_shared(sH);
  unsigned abase=shb+((((lane>>3)&1)*8+(lane&7))*528u)+((lane>>4)*16u);
  int j=w*8+tg*2;
  unsigned cst1[16],cst2[16];
  #pragma unroll
  for(int i=0;i<16;i++){cst1[i]=0u;cst2[i]=0u;}
  cpa16((char*)pan0+t*16,(const char*)g_w1+t*16);
  cpa16((char*)pan0+(t+512)*16,(const char*)g_w1+(t+512)*16);
  cpcommit();
  unsigned acc[8][4][2];
  for(int tt=0;tt<TSTEPS;tt++){
    // layer1 init: bias + x-MMA
    #pragma unroll
    for(int g=0;g<4;g++){int nb=g*128+j;unsigned bb=pk2f(sB1[nb],sB1[nb+1]);
      #pragma unroll
      for(int mt=0;mt<8;mt++){acc[mt][g][0]=bb;acc[mt][g][1]=bb;}}
    {
      unsigned b[4][2];
      #pragma unroll
      for(int g=0;g<4;g++){const unsigned* bp=&sWX[((g*16+w)*32+lane)*2];b[g][0]=bp[0];b[g][1]=bp[1];}
      const char* p=(const char*)sX;
      #pragma unroll
      for(int mt=0;mt<8;mt++){
        unsigned af[4];int r=mt*16+gid;int cb=tg*2;
        af[0]=*(const unsigned*)(p+(r*24+cb)*2);
        af[1]=*(const unsigned*)(p+((r+8)*24+cb)*2);
        af[2]=*(const unsigned*)(p+(r*24+cb+8)*2);
        af[3]=*(const unsigned*)(p+((r+8)*24+cb+8)*2);
        #pragma unroll
        for(int g=0;g<4;g++)MMAH(acc[mt][g][0],acc[mt][g][1],af,b[g][0],b[g][1]);}
    }
    for(int q=0;q<8;q++){
      cpwait();__syncthreads();
      {int nx=q+1;
       const char* src=(nx<8)?(const char*)(g_w1+nx*4096):(const char*)(g_w2+(nx-8)*4096);
       char* dst=(char*)((nx&1)?pan1:pan0);
       cpa16(dst+t*16,src+t*16);cpa16(dst+(t+512)*16,src+(t+512)*16);cpcommit();}
      chunkH(acc,abase,q*16,(q&1)?pan1:pan0,w,lane);
    }
    __syncthreads();
    #pragma unroll
    for(int mt=0;mt<8;mt++){
      #pragma unroll
      for(int reg=0;reg<2;reg++){
        unsigned i2=acc[mt][0][reg],f2=acc[mt][1][reg],g2=acc[mt][2][reg],o2=acc[mt][3][reg];
        unsigned cc=h2fma(sg2(f2),cst1[mt*2+reg],h2mul(sg2(i2),th2(g2)));
        cst1[mt*2+reg]=cc;
        unsigned hh=h2mul(sg2(o2),th2(cc));
        int r=mt*16+gid+reg*8;
        *(unsigned*)&sH[r*264+j]=hh;
      }
    }
    // layer2
    #pragma unroll
    for(int g=0;g<4;g++){int nb=g*128+j;unsigned bb=pk2f(sB2[nb],sB2[nb+1]);
      #pragma unroll
      for(int mt=0;mt<8;mt++){acc[mt][g][0]=bb;acc[mt][g][1]=bb;}}
    for(int q=8;q<24;q++){
      cpwait();__syncthreads();
      if(!(tt==TSTEPS-1&&q==23)){
       int nx=(q+1)%24;
       const char* src=(nx<8)?(const char*)(g_w1+nx*4096):(const char*)(g_w2+(nx-8)*4096);
       char* dst=(char*)((nx&1)?pan1:pan0);
       cpa16(dst+t*16,src+t*16);cpa16(dst+(t+512)*16,src+(t+512)*16);cpcommit();}
      chunkH(acc,abase,(q-8)*16,(q&1)?pan1:pan0,w,lane);
    }
    __syncthreads();
    #pragma unroll
    for(int mt=0;mt<8;mt++){
      #pragma unroll
      for(int reg=0;reg<2;reg++){
        unsigned i2=acc[mt][0][reg],f2=acc[mt][1][reg],g2=acc[mt][2][reg],o2=acc[mt][3][reg];
        unsigned cc=h2fma(sg2(f2),cst2[mt*2+reg],h2mul(sg2(i2),th2(g2)));
        cst2[mt*2+reg]=cc;
        unsigned hh=h2mul(sg2(o2),th2(cc));
        int r=mt*16+gid+reg*8;
        *(unsigned*)&sH[r*264+128+j]=hh;
        g_hout[((long)(node0+r)*12+tt)*64+(j>>1)]=hh;
      }
    }
  }
}

// ---------------- variance -> tconf ----------------
__global__ void k_var(int n){
  __shared__ float red[4][2];
  int t=threadIdx.x,u=t&63,sub=t>>6;
  int node=blockIdx.x*4+sub;
  float s1x=0,s2x=0,s1y=0,s2y=0;
  if(node<n){
    const unsigned* p=&g_hout[(long)node*12*64+u];
    #pragma unroll
    for(int tt=0;tt<12;tt++){
      unsigned v=p[tt*64];
      __half2 hv=*reinterpret_cast<__half2*>(&v);
      float hx=__low2float(hv),hy=__high2float(hv);
      s1x+=hx;s2x+=hx*hx;s1y+=hy;s2y+=hy*hy;}
  }
  float var=(s2x-s1x*s1x*(1.f/12.f))*(1.f/11.f)+(s2y-s1y*s1y*(1.f/12.f))*(1.f/11.f);
  #pragma unroll
  for(int off=16;off>0;off>>=1)var+=__shfl_xor_sync(0xffffffffu,var,off);
  if((t&31)==0)red[sub][(t>>5)&1]=var;
  __syncthreads();
  if(u==0&&node<n){
    float v=red[sub][0]+red[sub][1];
    g_tconf[node]=1.f/(1.f+v*(1.f/128.f));
  }
}

// ---------------- GAT edge scatter ----------------
__global__ void k_edge(const int* __restrict__ ei,long E,int n){
  long e=(long)blockIdx.x*blockDim.x+threadIdx.x;
  long tot=E+n; if(e>=tot)return;
  int s,d;
  if(e<E){s=ei[e];d=ei[E+e];}else{s=(int)(e-E);d=s;}
  float ex[HEADS];
  #pragma unroll
  for(int h=0;h<HEADS;h++){
    float v=g_as[s*HEADS+h]+g_ad[d*HEADS+h];
    v=(v>0.f)?v:0.2f*v;
    ex[h]=__expf(v);}
  red4(&g_ssum[(long)d*HEADS],ex[0],ex[1],ex[2],ex[3]);
  const float4* xs=(const float4*)&g_x[(long)s*HEADS*C];
  float* go=&g_gout[(long)d*HEADS*C];
  #pragma unroll
  for(int v=0;v<10;v++){
    float4 x4=xs[v];
    int j0=v*4;
    float a=ex[(j0  )/C]*x4.x, b=ex[(j0+1)/C]*x4.y,
          c=ex[(j0+2)/C]*x4.z, dd=ex[(j0+3)/C]*x4.w;
    red4(go+j0,a,b,c,dd);}
  red1(&g_deg[s],1.f);
  red1(&g_nsum[(long)d*C+g_lab[s]],1.f);
}

// ---------------- finalize ----------------
__global__ void k_final(const float* __restrict__ gb,float* __restrict__ out,int n){
  int i=blockIdx.x*blockDim.x+threadIdx.x;if(i>=n)return;
  float p[C],go[C];
  #pragma unroll
  for(int c=0;c<C;c++){p[c]=g_probs[i*C+c];go[c]=0.f;}
  #pragma unroll
  for(int h=0;h<HEADS;h++){
    float sh=g_ssum[i*HEADS+h]+1e-16f;float inv=1.f/sh;
    #pragma unroll
    for(int c=0;c<C;c++)go[c]+=g_gout[(long)i*HEADS*C+h*C+c]*inv;}
  float num=0.f,np=0.f,ng=0.f;
  #pragma unroll
  for(int c=0;c<C;c++){go[c]=go[c]*0.25f+gb[c];num+=p[c]*go[c];np+=p[c]*p[c];ng+=go[c]*go[c];}
  float den=fmaxf(sqrtf(np)*sqrtf(ng),1e-8f);
  float gconf=(num/den+1.f)*0.5f;
  float comb=0.4f*g_maxp[i]+0.2f*g_econf[i]+0.2f*g_tconf[i]+0.2f*gconf;
  int lab=g_lab[i];
  float navg=g_nsum[i*C+lab]/(g_deg[i]+1e-8f);
  float mask=((comb>0.85f)&&(navg>=0.6f))?1.f:0.f;
  out[i]=(float)lab; out[n+i]=comb; out[2*n+i]=mask; out[3*n+i]=g_maxp[i];
  out[4*n+i]=g_econf[i]; out[5*n+i]=g_tconf[i]; out[6*n+i]=gconf; out[7*n+i]=g_unc[i];
}

extern "C" void kernel_launch(void* const* d_in,const int* in_sizes,int n_in,
                              void* d_out,int out_size){
  const float* emb  =(const float*)d_in[0];
  const float* preds=(const float*)d_in[1];
  const int*   ei   =(const int*)  d_in[3];
  const float* cW1  =(const float*)d_in[4];
  const float* cb1  =(const float*)d_in[5];
  const float* cW2  =(const float*)d_in[6];
  const float* cb2  =(const float*)d_in[7];
  const float* w_ih0=(const float*)d_in[8];
  const float* w_hh0=(const float*)d_in[9];
  const float* b_ih0=(const float*)d_in[10];
  const float* b_hh0=(const float*)d_in[11];
  const float* w_ih1=(const float*)d_in[12];
  const float* w_hh1=(const float*)d_in[13];
  const float* b_ih1=(const float*)d_in[14];
  const float* b_hh1=(const float*)d_in[15];
  const float* gW   =(const float*)d_in[16];
  const float* gas  =(const float*)d_in[17];
  const float* gad  =(const float*)d_in[18];
  const float* gb   =(const float*)d_in[19];
  int n=in_sizes[1]/C;
  long E=in_sizes[3]/2;

  static cudaStream_t s1=nullptr;
  static cudaEvent_t evF=nullptr,evS=nullptr;
  if(!s1){
    cudaStreamCreateWithFlags(&s1,cudaStreamNonBlocking);
    cudaEventCreateWithFlags(&evF,cudaEventDisableTiming);
    cudaEventCreateWithFlags(&evS,cudaEventDisableTiming);
    cudaFuncSetAttribute(k_lstm,cudaFuncAttributeMaxDynamicSharedMemorySize,126976);
    cudaFuncSetAttribute(k_conf,cudaFuncAttributeMaxDynamicSharedMemorySize,32768);
  }

  cudaEventRecord(evF,0);
  cudaStreamWaitEvent(s1,evF,0);

  // main: weight pack -> lstm -> var
  k_prep_w<<<256,256>>>(w_ih0,w_hh0,w_ih1,w_hh1);
  k_lstm<<<(n+127)/128,512,126976>>>(preds,b_ih0,b_hh0,b_ih1,b_hh1,n);
  k_var<<<(n+3)/4,256>>>(n);

  // side: zero/transpose -> stage1 -> conf -> edge
  k_zero<<<2048,256,0,s1>>>(cW1,n);
  k_stage1<<<(n+255)/256,256,0,s1>>>(preds,gW,gas,gad,n);
  k_conf<<<(n+31)/32,256,32768,s1>>>(emb,cb1,cW2,cb2,n);
  long tot=E+n;
  k_edge<<<(int)((tot+255)/256),256,0,s1>>>(ei,E,n);
  cudaEventRecord(evS,s1);

  cudaStreamWaitEvent(0,evS,0);
  k_final<<<(n+255)/256,256>>>(gb,(float*)d_out,n);
}

// round 16
// speedup vs baseline: 1.0351x; 1.0351x over previous
#include <cuda_runtime.h>
#include <cuda_fp16.h>
#include <math.h>

#define MAXN 100000
#define HID 256
#define C 10
#define HEADS 4
#define TSTEPS 12

extern __shared__ char smem_dyn[];

__device__ unsigned g_wx[4096];
__device__ unsigned g_w1[8*4096];
__device__ unsigned g_w2[16*4096];
__device__ float g_cW1t[HID*128];
__device__ float g_probs[MAXN*C];
__device__ float g_x[MAXN*HEADS*C];
__device__ float g_as[MAXN*HEADS];
__device__ float g_ad[MAXN*HEADS];
__device__ float g_ssum[MAXN*HEADS];
__device__ float g_gout[MAXN*HEADS*C];
__device__ float g_deg[MAXN];
__device__ float g_nsum[MAXN*C];
__device__ float g_econf[MAXN];
__device__ float g_tconf[MAXN];
__device__ float g_maxp[MAXN];
__device__ float g_unc[MAXN];
__device__ int   g_lab[MAXN];

__device__ __forceinline__ unsigned pkhf(float a,float b){
  return (unsigned)__half_as_ushort(__float2half(a))
       |((unsigned)__half_as_ushort(__float2half(b))<<16);}
__device__ __forceinline__ unsigned pk2f(float lo,float hi){
  unsigned r;asm("cvt.rn.f16x2.f32 %0,%1,%2;":"=r"(r):"f"(hi),"f"(lo));return r;}
__device__ __forceinline__ unsigned th2(unsigned x){unsigned y;asm("tanh.approx.f16x2 %0,%1;":"=r"(y):"r"(x));return y;}
__device__ __forceinline__ unsigned h2mul(unsigned a,unsigned b){unsigned r;asm("mul.f16x2 %0,%1,%2;":"=r"(r):"r"(a),"r"(b));return r;}
__device__ __forceinline__ unsigned h2fma(unsigned a,unsigned b,unsigned c){unsigned r;asm("fma.rn.f16x2 %0,%1,%2,%3;":"=r"(r):"r"(a),"r"(b),"r"(c));return r;}
#define H05 0x38003800u
__device__ __forceinline__ unsigned sg2(unsigned x){return h2fma(th2(h2mul(x,H05)),H05,H05);}
__device__ __forceinline__ void cpa16(char* s,const char* g){unsigned a=(unsigned)__cvta_generic_to_shared(s);asm volatile("cp.async.cg.shared.global [%0],[%1],16;"::"r"(a),"l"(g));}
__device__ __forceinline__ void cpcommit(){asm volatile("cp.async.commit_group;");}
__device__ __forceinline__ void cpwait(){asm volatile("cp.async.wait_group 0;");}
__device__ __forceinline__ void red4(float* p,float a,float b,float c,float d){
  asm volatile("red.global.add.v4.f32 [%0],{%1,%2,%3,%4};"::"l"(p),"f"(a),"f"(b),"f"(c),"f"(d):"memory");}
__device__ __forceinline__ void red1(float* p,float a){
  asm volatile("red.global.add.f32 [%0],%1;"::"l"(p),"f"(a):"memory");}
#define MMAH(c0,c1,a,b0,b1) asm volatile("mma.sync.aligned.m16n8k16.row.col.f16.f16.f16.f16 {%0,%1},{%2,%3,%4,%5},{%6,%7},{%0,%1};":"+r"(c0),"+r"(c1):"r"(a[0]),"r"(a[1]),"r"(a[2]),"r"(a[3]),"r"(b0),"r"(b1))

// ---------------- prep (weights only, main stream) ----------------
__global__ void k_prep_w(const float* __restrict__ w_ih0,const float* __restrict__ w_hh0,
                         const float* __restrict__ w_ih1,const float* __restrict__ w_hh1){
  long i=(long)blockIdx.x*blockDim.x+threadIdx.x; long st=(long)gridDim.x*blockDim.x;
  for(long idx=i;idx<4096;idx+=st){
    int reg=(int)idx&1,lane=((int)idx>>1)&31,nt=(int)idx>>6;
    int nn=nt*8+(lane>>2),k0=(lane&3)*2+reg*8;
    float lo=(k0<C)?w_ih0[nn*C+k0]:0.f,hi=(k0+1<C)?w_ih0[nn*C+k0+1]:0.f;
    g_wx[idx]=pkhf(lo,hi);}
  for(long idx=i;idx<8*4096;idx+=st){
    int kc=(int)idx>>12,r=(int)idx&4095,reg=r&1,lane=(r>>1)&31,nt=r>>6;
    int nn=nt*8+(lane>>2),k0=kc*16+(lane&3)*2+reg*8;
    g_w1[idx]=pkhf(w_hh0[nn*128+k0],w_hh0[nn*128+k0+1]);}
  for(long idx=i;idx<16*4096;idx+=st){
    int kc=(int)idx>>12,r=(int)idx&4095,reg=r&1,lane=(r>>1)&31,nt=r>>6;
    int nn=nt*8+(lane>>2),k0=kc*16+(lane&3)*2+reg*8;
    float lo=(k0<128)?w_ih1[nn*128+k0]:w_hh1[nn*128+k0-128];
    float hi=(k0<128)?w_ih1[nn*128+k0+1]:w_hh1[nn*128+k0-127];
    g_w2[idx]=pkhf(lo,hi);}
}

// ---------------- zero + cW1 transpose (side stream) ----------------
__global__ void k_zero(const float* __restrict__ cW1,int n){
  long i=(long)blockIdx.x*blockDim.x+threadIdx.x; long st=(long)gridDim.x*blockDim.x;
  for(long idx=i;idx<HID*128;idx+=st){int k=(int)(idx/128),o=(int)(idx%128);g_cW1t[idx]=cW1[o*HID+k];}
  for(long idx=i;idx<(long)n*HEADS;idx+=st)g_ssum[idx]=0.f;
  for(long idx=i;idx<(long)n*HEADS*C;idx+=st)g_gout[idx]=0.f;
  for(long idx=i;idx<n;idx+=st)g_deg[idx]=0.f;
  for(long idx=i;idx<(long)n*C;idx+=st)g_nsum[idx]=0.f;
}

// ---------------- stage1 ----------------
__global__ void k_stage1(const float* __restrict__ preds,const float* __restrict__ gW,
                         const float* __restrict__ gas,const float* __restrict__ gad,int n){
  __shared__ float sgW[C*HEADS*C],sas[HEADS*C],sad[HEADS*C];
  int t=threadIdx.x;
  for(int i=t;i<C*HEADS*C;i+=blockDim.x)sgW[i]=gW[i];
  if(t<HEADS*C){sas[t]=gas[t];sad[t]=gad[t];}
  __syncthreads();
  int i=blockIdx.x*blockDim.x+t; if(i>=n)return;
  float p[C];float m=-1e30f;
  #pragma unroll
  for(int c=0;c<C;c++){p[c]=preds[i*C+c];m=fmaxf(m,p[c]);}
  float s=0.f;
  #pragma unroll
  for(int c=0;c<C;c++){p[c]=expf(p[c]-m);s+=p[c];}
  float inv=1.f/s;int lab=0;float mp=-1.f,ent=0.f;
  #pragma unroll
  for(int c=0;c<C;c++){p[c]*=inv;if(p[c]>mp){mp=p[c];lab=c;}}
  #pragma unroll
  for(int c=0;c<C;c++){ent-=p[c]*logf(p[c]+1e-8f);g_probs[i*C+c]=p[c];}
  g_lab[i]=lab;g_maxp[i]=mp;g_unc[i]=ent/2.302585093f;
  float xv[HEADS*C];
  #pragma unroll
  for(int hc=0;hc<HEADS*C;hc++){float a=0.f;
    #pragma unroll
    for(int c=0;c<C;c++)a+=p[c]*sgW[c*(HEADS*C)+hc];
    xv[hc]=a;g_x[(long)i*(HEADS*C)+hc]=a;}
  #pragma unroll
  for(int h=0;h<HEADS;h++){float a=0.f,b=0.f;
    #pragma unroll
    for(int c=0;c<C;c++){a+=xv[h*C+c]*sas[h*C+c];b+=xv[h*C+c]*sad[h*C+c];}
    g_as[i*HEADS+h]=a;g_ad[i*HEADS+h]=b;}
}

// ---------------- confidence net: 32 nodes/CTA, W1 from L2 ----------------
__global__ void __launch_bounds__(256) k_conf(const float* __restrict__ emb,const float* __restrict__ cb1,
                                              const float* __restrict__ cW2,const float* __restrict__ cb2,int n){
  float* sE=(float*)smem_dyn;
  int t=threadIdx.x;int node0=blockIdx.x*32;
  for(int idx=t;idx<8192;idx+=256){int nl=idx>>8,k=idx&255;sE[idx]=(node0+nl<n)?emb[(long)(node0+nl)*HID+k]:0.f;}
  __syncthreads();
  int j4=t&31,r=t>>5;
  float acc[4][4];
  #pragma unroll
  for(int a=0;a<4;a++){acc[a][0]=0;acc[a][1]=0;acc[a][2]=0;acc[a][3]=0;}
  for(int k=0;k<HID;k+=4){
    float4 w0=__ldg((const float4*)&g_cW1t[(k+0)*128+j4*4]);
    float4 w1=__ldg((const float4*)&g_cW1t[(k+1)*128+j4*4]);
    float4 w2=__ldg((const float4*)&g_cW1t[(k+2)*128+j4*4]);
    float4 w3=__ldg((const float4*)&g_cW1t[(k+3)*128+j4*4]);
    #pragma unroll
    for(int i=0;i<4;i++){
      float4 e=*(const float4*)&sE[(r*4+i)*HID+k];
      acc[i][0]=fmaf(e.x,w0.x,fmaf(e.y,w1.x,fmaf(e.z,w2.x,fmaf(e.w,w3.x,acc[i][0]))));
      acc[i][1]=fmaf(e.x,w0.y,fmaf(e.y,w1.y,fmaf(e.z,w2.y,fmaf(e.w,w3.y,acc[i][1]))));
      acc[i][2]=fmaf(e.x,w0.z,fmaf(e.y,w1.z,fmaf(e.z,w2.z,fmaf(e.w,w3.z,acc[i][2]))));
      acc[i][3]=fmaf(e.x,w0.w,fmaf(e.y,w1.w,fmaf(e.z,w2.w,fmaf(e.w,w3.w,acc[i][3]))));}}
  float b1[4],w2v[4];
  #pragma unroll
  for(int cc=0;cc<4;cc++){b1[cc]=cb1[j4*4+cc];w2v[cc]=cW2[j4*4+cc];}
  float b2=cb2[0];
  #pragma unroll
  for(int i=0;i<4;i++){
    float pi=0.f;
    #pragma unroll
    for(int cc=0;cc<4;cc++){float h=fmaxf(acc[i][cc]+b1[cc],0.f);pi=fmaf(h,w2v[cc],pi);}
    #pragma unroll
    for(int off=16;off>0;off>>=1)pi+=__shfl_xor_sync(0xffffffffu,pi,off);
    if(j4==0){int node=node0+r*4+i;if(node<n)g_econf[node]=1.f/(1.f+__expf(-(pi+b2)));}
  }
}

// ---------------- LSTM: f16-acc mma, 64 nodes/CTA (R14 structure) ----------------
__device__ __forceinline__ void chunkH(unsigned acc[4][4][2],unsigned abase,int kb,
                                       const unsigned* pan,int w,int lane){
  unsigned b[4][2];
  #pragma unroll
  for(int g=0;g<4;g++){const unsigned* bp=&pan[((g*16+w)*32+lane)*2];b[g][0]=bp[0];b[g][1]=bp[1];}
  #pragma unroll
  for(int mt=0;mt<4;mt++){
    unsigned af[4];
    unsigned a=abase+mt*16*528+kb*2;
    asm volatile("ldmatrix.sync.aligned.m8n8.x4.shared.b16 {%0,%1,%2,%3},[%4];"
      :"=r"(af[0]),"=r"(af[1]),"=r"(af[2]),"=r"(af[3]):"r"(a));
    #pragma unroll
    for(int g=0;g<4;g++)MMAH(acc[mt][g][0],acc[mt][g][1],af,b[g][0],b[g][1]);
  }
}

__global__ void __launch_bounds__(512,1) k_lstm(const float* __restrict__ preds,
    const float* __restrict__ b_ih0,const float* __restrict__ b_hh0,
    const float* __restrict__ b_ih1,const float* __restrict__ b_hh1,int n){
  char* sm=smem_dyn;
  unsigned* pan0=(unsigned*)sm; unsigned* pan1=(unsigned*)(sm+16384);
  unsigned* sWX=(unsigned*)(sm+32768);
  __half* sH=(__half*)(sm+49152);
  __half* sX=(__half*)(sm+82944);
  float* sB1=(float*)(sm+86016);
  float* sB2=(float*)(sm+88064);
  float* sVar=(float*)(sm+90112);
  float* sRed=(float*)(sm+155648);
  int t=threadIdx.x,w=t>>5,lane=t&31,gid=lane>>2,tg=lane&3;
  int node0=blockIdx.x*64;
  for(int idx=t;idx<1024;idx+=512){int r=idx>>4,c2=idx&15;
    sX[r*24+c2]=__float2half((c2<C&&node0+r<n)?preds[(long)(node0+r)*C+c2]:0.f);}
  for(int idx=t;idx<4096;idx+=512)sWX[idx]=g_wx[idx];
  sB1[t]=b_ih0[t]+b_hh0[t]; sB2[t]=b_ih1[t]+b_hh1[t];
  for(int idx=t;idx<8448;idx+=512)((unsigned*)sH)[idx]=0;
  if(t<64)sRed[t]=0.f;
  __syncthreads();
  unsigned shb=(unsigned)__cvta_generic_to_shared(sH);
  unsigned abase=shb+((((lane>>3)&1)*8+(lane&7))*528u)+((lane>>4)*16u);
  int j=w*8+tg*2;
  unsigned cst1[8],cst2[8];
  #pragma unroll
  for(int i=0;i<8;i++){cst1[i]=0u;cst2[i]=0u;}
  cpa16((char*)pan0+t*16,(const char*)g_w1+t*16);
  cpa16((char*)pan0+(t+512)*16,(const char*)g_w1+(t+512)*16);
  cpcommit();
  unsigned acc[4][4][2];
  for(int tt=0;tt<TSTEPS;tt++){
    #pragma unroll
    for(int g=0;g<4;g++){int nb=g*128+j;unsigned bb=pk2f(sB1[nb],sB1[nb+1]);
      #pragma unroll
      for(int mt=0;mt<4;mt++){acc[mt][g][0]=bb;acc[mt][g][1]=bb;}}
    {
      unsigned b[4][2];
      #pragma unroll
      for(int g=0;g<4;g++){const unsigned* bp=&sWX[((g*16+w)*32+lane)*2];b[g][0]=bp[0];b[g][1]=bp[1];}
      const char* p=(const char*)sX;
      #pragma unroll
      for(int mt=0;mt<4;mt++){
        unsigned af[4];int r=mt*16+gid;int cb=tg*2;
        af[0]=*(const unsigned*)(p+(r*24+cb)*2);
        af[1]=*(const unsigned*)(p+((r+8)*24+cb)*2);
        af[2]=*(const unsigned*)(p+(r*24+cb+8)*2);
        af[3]=*(const unsigned*)(p+((r+8)*24+cb+8)*2);
        #pragma unroll
        for(int g=0;g<4;g++)MMAH(acc[mt][g][0],acc[mt][g][1],af,b[g][0],b[g][1]);}
    }
    for(int q=0;q<8;q++){
      cpwait();__syncthreads();
      {int nx=q+1;
       const char* src=(nx<8)?(const char*)(g_w1+nx*4096):(const char*)(g_w2+(nx-8)*4096);
       char* dst=(char*)((nx&1)?pan1:pan0);
       cpa16(dst+t*16,src+t*16);cpa16(dst+(t+512)*16,src+(t+512)*16);cpcommit();}
      chunkH(acc,abase,q*16,(q&1)?pan1:pan0,w,lane);
    }
    __syncthreads();
    #pragma unroll
    for(int mt=0;mt<4;mt++){
      #pragma unroll
      for(int reg=0;reg<2;reg++){
        unsigned i2=acc[mt][0][reg],f2=acc[mt][1][reg],g2=acc[mt][2][reg],o2=acc[mt][3][reg];
        unsigned cc=h2fma(sg2(f2),cst1[mt*2+reg],h2mul(sg2(i2),th2(g2)));
        cst1[mt*2+reg]=cc;
        unsigned hh=h2mul(sg2(o2),th2(cc));
        int r=mt*16+gid+reg*8;
        *(unsigned*)&sH[r*264+j]=hh;
      }
    }
    #pragma unroll
    for(int g=0;g<4;g++){int nb=g*128+j;unsigned bb=pk2f(sB2[nb],sB2[nb+1]);
      #pragma unroll
      for(int mt=0;mt<4;mt++){acc[mt][g][0]=bb;acc[mt][g][1]=bb;}}
    for(int q=8;q<24;q++){
      cpwait();__syncthreads();
      if(!(tt==TSTEPS-1&&q==23)){
       int nx=(q+1)%24;
       const char* src=(nx<8)?(const char*)(g_w1+nx*4096):(const char*)(g_w2+(nx-8)*4096);
       char* dst=(char*)((nx&1)?pan1:pan0);
       cpa16(dst+t*16,src+t*16);cpa16(dst+(t+512)*16,src+(t+512)*16);cpcommit();}
      chunkH(acc,abase,(q-8)*16,(q&1)?pan1:pan0,w,lane);
    }
    __syncthreads();
    #pragma unroll
    for(int mt=0;mt<4;mt++){
      #pragma unroll
      for(int reg=0;reg<2;reg++){
        unsigned i2=acc[mt][0][reg],f2=acc[mt][1][reg],g2=acc[mt][2][reg],o2=acc[mt][3][reg];
        unsigned cc=h2fma(sg2(f2),cst2[mt*2+reg],h2mul(sg2(i2),th2(g2)));
        cst2[mt*2+reg]=cc;
        unsigned hh=h2mul(sg2(o2),th2(cc));
        int r=mt*16+gid+reg*8;
        *(unsigned*)&sH[r*264+128+j]=hh;
        __half2 hv=*reinterpret_cast<__half2*>(&hh);
        float hx=__low2float(hv),hy=__high2float(hv);
        int s0=mt*4+reg*2;
        if(tt==0){sVar[s0*512+t]=hx;sVar[8192+s0*512+t]=hx*hx;
                  sVar[(s0+1)*512+t]=hy;sVar[8192+(s0+1)*512+t]=hy*hy;}
        else{sVar[s0*512+t]+=hx;sVar[8192+s0*512+t]+=hx*hx;
             sVar[(s0+1)*512+t]+=hy;sVar[8192+(s0+1)*512+t]+=hy*hy;}
      }
    }
  }
  __syncthreads();
  #pragma unroll
  for(int mt=0;mt<4;mt++)
    #pragma unroll
    for(int q=0;q<4;q++){
      int s=mt*4+q;
      float a=sVar[s*512+t],b=sVar[8192+s*512+t];
      float var=(b-a*a*(1.f/12.f))*(1.f/11.f);
      atomicAdd(&sRed[mt*16+gid+((q>=2)?8:0)],var);}
  __syncthreads();
  if(t<64){int node=node0+t;if(node<n)g_tconf[node]=1.f/(1.f+sRed[t]*(1.f/128.f));}
}

// ---------------- GAT edge scatter ----------------
__global__ void k_edge(const int* __restrict__ ei,long E,int n){
  long e=(long)blockIdx.x*blockDim.x+threadIdx.x;
  long tot=E+n; if(e>=tot)return;
  int s,d;
  if(e<E){s=ei[e];d=ei[E+e];}else{s=(int)(e-E);d=s;}
  float ex[HEADS];
  #pragma unroll
  for(int h=0;h<HEADS;h++){
    float v=g_as[s*HEADS+h]+g_ad[d*HEADS+h];
    v=(v>0.f)?v:0.2f*v;
    ex[h]=__expf(v);}
  red4(&g_ssum[(long)d*HEADS],ex[0],ex[1],ex[2],ex[3]);
  const float4* xs=(const float4*)&g_x[(long)s*HEADS*C];
  float* go=&g_gout[(long)d*HEADS*C];
  #pragma unroll
  for(int v=0;v<10;v++){
    float4 x4=xs[v];
    int j0=v*4;
    float a=ex[(j0  )/C]*x4.x, b=ex[(j0+1)/C]*x4.y,
          c=ex[(j0+2)/C]*x4.z, dd=ex[(j0+3)/C]*x4.w;
    red4(go+j0,a,b,c,dd);}
  red1(&g_deg[s],1.f);
  red1(&g_nsum[(long)d*C+g_lab[s]],1.f);
}

// ---------------- finalize ----------------
__global__ void k_final(const float* __restrict__ gb,float* __restrict__ out,int n){
  int i=blockIdx.x*blockDim.x+threadIdx.x;if(i>=n)return;
  float p[C],go[C];
  #pragma unroll
  for(int c=0;c<C;c++){p[c]=g_probs[i*C+c];go[c]=0.f;}
  #pragma unroll
  for(int h=0;h<HEADS;h++){
    float sh=g_ssum[i*HEADS+h]+1e-16f;float inv=1.f/sh;
    #pragma unroll
    for(int c=0;c<C;c++)go[c]+=g_gout[(long)i*HEADS*C+h*C+c]*inv;}
  float num=0.f,np=0.f,ng=0.f;
  #pragma unroll
  for(int c=0;c<C;c++){go[c]=go[c]*0.25f+gb[c];num+=p[c]*go[c];np+=p[c]*p[c];ng+=go[c]*go[c];}
  float den=fmaxf(sqrtf(np)*sqrtf(ng),1e-8f);
  float gconf=(num/den+1.f)*0.5f;
  float comb=0.4f*g_maxp[i]+0.2f*g_econf[i]+0.2f*g_tconf[i]+0.2f*gconf;
  int lab=g_lab[i];
  float navg=g_nsum[i*C+lab]/(g_deg[i]+1e-8f);
  float mask=((comb>0.85f)&&(navg>=0.6f))?1.f:0.f;
  out[i]=(float)lab; out[n+i]=comb; out[2*n+i]=mask; out[3*n+i]=g_maxp[i];
  out[4*n+i]=g_econf[i]; out[5*n+i]=g_tconf[i]; out[6*n+i]=gconf; out[7*n+i]=g_unc[i];
}

extern "C" void kernel_launch(void* const* d_in,const int* in_sizes,int n_in,
                              void* d_out,int out_size){
  const float* emb  =(const float*)d_in[0];
  const float* preds=(const float*)d_in[1];
  const int*   ei   =(const int*)  d_in[3];
  const float* cW1  =(const float*)d_in[4];
  const float* cb1  =(const float*)d_in[5];
  const float* cW2  =(const float*)d_in[6];
  const float* cb2  =(const float*)d_in[7];
  const float* w_ih0=(const float*)d_in[8];
  const float* w_hh0=(const float*)d_in[9];
  const float* b_ih0=(const float*)d_in[10];
  const float* b_hh0=(const float*)d_in[11];
  const float* w_ih1=(const float*)d_in[12];
  const float* w_hh1=(const float*)d_in[13];
  const float* b_ih1=(const float*)d_in[14];
  const float* b_hh1=(const float*)d_in[15];
  const float* gW   =(const float*)d_in[16];
  const float* gas  =(const float*)d_in[17];
  const float* gad  =(const float*)d_in[18];
  const float* gb   =(const float*)d_in[19];
  int n=in_sizes[1]/C;
  long E=in_sizes[3]/2;

  static cudaStream_t s1=nullptr;
  static cudaEvent_t evF=nullptr,evS=nullptr;
  if(!s1){
    cudaStreamCreateWithFlags(&s1,cudaStreamNonBlocking);
    cudaEventCreateWithFlags(&evF,cudaEventDisableTiming);
    cudaEventCreateWithFlags(&evS,cudaEventDisableTiming);
    cudaFuncSetAttribute(k_lstm,cudaFuncAttributeMaxDynamicSharedMemorySize,155904);
    cudaFuncSetAttribute(k_conf,cudaFuncAttributeMaxDynamicSharedMemorySize,32768);
  }

  cudaEventRecord(evF,0);
  cudaStreamWaitEvent(s1,evF,0);

  // main: weight pack -> lstm
  k_prep_w<<<256,256>>>(w_ih0,w_hh0,w_ih1,w_hh1);
  k_lstm<<<(n+63)/64,512,155904>>>(preds,b_ih0,b_hh0,b_ih1,b_hh1,n);

  // side: zero/transpose -> stage1 -> conf -> edge
  k_zero<<<2048,256,0,s1>>>(cW1,n);
  k_stage1<<<(n+255)/256,256,0,s1>>>(preds,gW,gas,gad,n);
  k_conf<<<(n+31)/32,256,32768,s1>>>(emb,cb1,cW2,cb2,n);
  long tot=E+n;
  k_edge<<<(int)((tot+255)/256),256,0,s1>>>(ei,E,n);
  cudaEventRecord(evS,s1);

  cudaStreamWaitEvent(0,evS,0);
  k_final<<<(n+255)/256,256>>>(gb,(float*)d_out,n);
}